// round 14
// baseline (speedup 1.0000x reference)
#include <cuda_runtime.h>
#include <cuda.h>
#include <cuda_fp16.h>
#include <cstdint>

// ---------------- problem constants ----------------
#define B_BATCH 64
#define S_LEN   2048
#define D_DIM   1024
#define ROWS_TOTAL (B_BATCH * S_LEN)   // 131072

// ---------------- GEMM tiling ----------------
#define TILE_M 128
#define TILE_N 128
#define KC     64                      // k per stage (fp16 -> 128B rows)
#define KITERS (D_DIM / KC)            // 16
#define NPART  8                       // D_DIM / TILE_N
#define GEMM_THREADS 128               // 4 warps, 2m x 2n, warp tile 64x64
#define NSTAGES 3

#define A_STAGE_B (TILE_M * KC * 2)    // 16384 B
#define B_STAGE_B (TILE_N * KC * 2)    // 16384 B

#define SM_W2 0
#define SM_V  512
#define SM_E  1024                     // 256 floats
#define SM_A  2048
#define SM_B  (SM_A + NSTAGES * A_STAGE_B)        // 51200
#define SMEM_TOTAL (SM_B + NSTAGES * B_STAGE_B)   // 100352 B (2 CTAs/SM)

#define CTX_SPLIT 16                   // context split-S factor

// ---------------- scratch ----------------
__device__ __half g_enc_h[(size_t)ROWS_TOTAL * D_DIM];   // enc as fp16
__device__ __half g_w1e_h[D_DIM * D_DIM];                // W1e as fp16 (k-major)
__device__ float g_v[B_BATCH * D_DIM];                   // h@W1h^T + b1
__device__ float g_e_part[NPART * ROWS_TOTAL];           // per n-part partial e
__device__ float g_alpha[ROWS_TOTAL];
__device__ float g_ctx_part[CTX_SPLIT * B_BATCH * D_DIM];// split-S context partials

// ---------------- helpers ----------------
__device__ __forceinline__ uint32_t smem_u32(const void* p) {
    uint32_t a;
    asm("{ .reg .u64 t; cvta.to.shared.u64 t, %1; cvt.u32.u64 %0, t; }" : "=r"(a) : "l"(p));
    return a;
}
__device__ __forceinline__ void cp16(uint32_t smem_addr, const void* gptr) {
    asm volatile("cp.async.cg.shared.global [%0], [%1], 16;" :: "r"(smem_addr), "l"(gptr));
}
#define CP_COMMIT() asm volatile("cp.async.commit_group;" ::: "memory")
#define CP_WAIT(n)  asm volatile("cp.async.wait_group %0;" :: "n"(n) : "memory")

__device__ __forceinline__ void ldsm4(uint32_t* r, uint32_t addr) {
    asm volatile("ldmatrix.sync.aligned.m8n8.x4.shared.b16 {%0,%1,%2,%3}, [%4];"
        : "=r"(r[0]), "=r"(r[1]), "=r"(r[2]), "=r"(r[3]) : "r"(addr));
}
__device__ __forceinline__ void mma_f16(float* d, const uint32_t* a, uint32_t b0, uint32_t b1) {
    asm volatile(
        "mma.sync.aligned.m16n8k16.row.col.f32.f16.f16.f32 "
        "{%0,%1,%2,%3}, {%4,%5,%6,%7}, {%8,%9}, {%0,%1,%2,%3};"
        : "+f"(d[0]), "+f"(d[1]), "+f"(d[2]), "+f"(d[3])
        : "r"(a[0]), "r"(a[1]), "r"(a[2]), "r"(a[3]), "r"(b0), "r"(b1));
}
__device__ __forceinline__ float tanhf_fast(float x) {
    float t;
    asm("tanh.approx.f32 %0, %1;" : "=f"(t) : "f"(x));
    return t;
}

// ---------------- kernel 1: fused prep (v | pack W1e | conv enc) ----------------
#define PREP_BLOCKS (1024 + 512 + 65536)
__global__ void prep_kernel(const float* __restrict__ enc, const float* __restrict__ W1,
                            const float* __restrict__ b1, const float* __restrict__ hidden) {
    __shared__ float hs[1024];
    const int bid = blockIdx.x;
    const int tid = threadIdx.x;
    if (bid < 1024) {
        int b = bid & 63, yseg = bid >> 6;
        int w = tid >> 5, lane = tid & 31;
        for (int i = tid; i < 1024; i += 256) hs[i] = hidden[b * 1024 + i];
        __syncthreads();
        #pragma unroll
        for (int i = 0; i < 8; i++) {
            int d = yseg * 64 + w * 8 + i;
            const float* row = W1 + (size_t)d * 2048 + 1024;
            float acc = 0.f;
            for (int m = lane; m < 1024; m += 32) acc = fmaf(hs[m], row[m], acc);
            #pragma unroll
            for (int o = 16; o; o >>= 1) acc += __shfl_xor_sync(0xFFFFFFFFu, acc, o);
            if (lane == 0) g_v[b * 1024 + d] = acc + b1[d];
        }
    } else if (bid < 1536) {
        int t = (bid - 1024) * 256 + tid;
        size_t base = (size_t)t * 8;
        int d = (int)(base >> 10);
        int k = (int)(base & 1023);
        const float4* src = (const float4*)(W1 + (size_t)d * 2048 + k);
        float4 v0 = src[0], v1 = src[1];
        __half2 h[4];
        h[0] = __floats2half2_rn(v0.x, v0.y);
        h[1] = __floats2half2_rn(v0.z, v0.w);
        h[2] = __floats2half2_rn(v1.x, v1.y);
        h[3] = __floats2half2_rn(v1.z, v1.w);
        *(uint4*)(g_w1e_h + (size_t)d * 1024 + k) = *(uint4*)h;
    } else {
        size_t i = ((size_t)(bid - 1536) * 256 + tid) * 8;
        float4 v0 = *(const float4*)(enc + i);
        float4 v1 = *(const float4*)(enc + i + 4);
        __half2 h[4];
        h[0] = __floats2half2_rn(v0.x, v0.y);
        h[1] = __floats2half2_rn(v0.z, v0.w);
        h[2] = __floats2half2_rn(v1.x, v1.y);
        h[3] = __floats2half2_rn(v1.z, v1.w);
        *(uint4*)(g_enc_h + i) = *(uint4*)h;
    }
}

// ---------------- kernel 2: GEMM (mma.sync fp16) + tanh + W2-dot ----------------
// 128 threads, 4 warps: 2m x 2n; warp tile 64x64. 2 CTAs/SM.
// Prefetch cp.asyncs distributed: A-half after ks0, B-half after ks1, commit, ks2, ks3.
__global__ void __launch_bounds__(GEMM_THREADS, 2)
gemm_tanh_kernel(const float* __restrict__ W2) {
    extern __shared__ char smem[];
    const int tid = threadIdx.x;
    const int wid = tid >> 5;
    const int lane = tid & 31;
    const int wm = wid & 1;
    const int wn = wid >> 1;
    const int qid = lane >> 2;
    const int qtid = lane & 3;
    const int d0 = blockIdx.x * TILE_N;
    const int row0 = blockIdx.y * TILE_M;
    const int b = row0 / S_LEN;

    float* W2s = (float*)(smem + SM_W2);
    float* vs  = (float*)(smem + SM_V);
    W2s[tid] = W2[d0 + tid];
    vs[tid]  = g_v[b * 1024 + d0 + tid];

    const uint32_t sA = smem_u32(smem + SM_A);
    const uint32_t sB = smem_u32(smem + SM_B);

    auto load_A = [&](int stg, int kc) {
        #pragma unroll
        for (int i = 0; i < 8; i++) {
            int j = tid + i * 128;
            int r = j >> 3, ck = j & 7;
            cp16(sA + stg * A_STAGE_B + (uint32_t)(r * 128 + ((ck ^ (r & 7)) << 4)),
                 g_enc_h + (size_t)(row0 + r) * 1024 + kc * KC + ck * 8);
        }
    };
    auto load_B = [&](int stg, int kc) {
        #pragma unroll
        for (int i = 0; i < 8; i++) {
            int j = tid + i * 128;
            int n = j >> 3, ck = j & 7;
            cp16(sB + stg * B_STAGE_B + (uint32_t)(n * 128 + ((ck ^ (n & 7)) << 4)),
                 g_w1e_h + (size_t)(d0 + n) * 1024 + kc * KC + ck * 8);
        }
    };

    const int mlane = (lane & 7) | (lane & 8);
    const int cbitA = (lane >> 4) & 1;
    const int nlane = (lane & 7) | ((lane & 16) >> 1);
    const int cbitB = (lane >> 3) & 1;
    int rA0 = wm * 64 + mlane;
    int phA = rA0 & 7;
    int rB0 = wn * 64 + nlane;
    int phB = rB0 & 7;

    float c[4][8][4];
    #pragma unroll
    for (int mt = 0; mt < 4; mt++)
        #pragma unroll
        for (int nt = 0; nt < 8; nt++)
            #pragma unroll
            for (int q = 0; q < 4; q++) c[mt][nt][q] = 0.f;

    load_A(0, 0); load_B(0, 0); CP_COMMIT();
    load_A(1, 1); load_B(1, 1); CP_COMMIT();

    int cur = 0;
    for (int kc = 0; kc < KITERS; kc++) {
        CP_WAIT(1);
        __syncthreads();

        const uint32_t sAc = sA + cur * A_STAGE_B;
        const uint32_t sBc = sB + cur * B_STAGE_B;

        auto do_ks = [&](int ks) {
            uint32_t bb[8][2];
            #pragma unroll
            for (int ntp = 0; ntp < 4; ntp++) {
                uint32_t q[4];
                uint32_t addr = sBc + (uint32_t)((rB0 + ntp * 16) * 128)
                              + (uint32_t)((((2 * ks + cbitB) ^ phB)) << 4);
                ldsm4(q, addr);
                bb[ntp * 2][0] = q[0]; bb[ntp * 2][1] = q[1];
                bb[ntp * 2 + 1][0] = q[2]; bb[ntp * 2 + 1][1] = q[3];
            }
            uint32_t a[4][4];
            ldsm4(a[0], sAc + (uint32_t)(rA0 * 128) + (uint32_t)((((2 * ks + cbitA) ^ phA)) << 4));
            #pragma unroll
            for (int mt = 0; mt < 4; mt++) {
                if (mt + 1 < 4)
                    ldsm4(a[mt + 1], sAc + (uint32_t)((rA0 + (mt + 1) * 16) * 128)
                                   + (uint32_t)((((2 * ks + cbitA) ^ phA)) << 4));
                #pragma unroll
                for (int nt = 0; nt < 8; nt++)
                    mma_f16(c[mt][nt], a[mt], bb[nt][0], bb[nt][1]);
            }
        };

        int nxt = cur + 2; if (nxt >= NSTAGES) nxt -= NSTAGES;
        bool pf = (kc + 2 < KITERS);

        do_ks(0);
        if (pf) load_A(nxt, kc + 2);        // A-half of prefetch
        do_ks(1);
        if (pf) load_B(nxt, kc + 2);        // B-half of prefetch
        CP_COMMIT();
        do_ks(2);
        do_ks(3);

        cur++; if (cur >= NSTAGES) cur -= NSTAGES;
    }

    // ---------------- fused epilogue ----------------
    float eacc[4][2];
    #pragma unroll
    for (int mt = 0; mt < 4; mt++) { eacc[mt][0] = 0.f; eacc[mt][1] = 0.f; }
    #pragma unroll
    for (int mt = 0; mt < 4; mt++) {
        #pragma unroll
        for (int nt = 0; nt < 8; nt++) {
            int n0 = wn * 64 + nt * 8 + 2 * qtid;
            int n1 = n0 + 1;
            float w0 = W2s[n0], w1 = W2s[n1];
            float v0 = vs[n0],  v1 = vs[n1];
            eacc[mt][0] = fmaf(tanhf_fast(c[mt][nt][0] + v0), w0, eacc[mt][0]);
            eacc[mt][0] = fmaf(tanhf_fast(c[mt][nt][1] + v1), w1, eacc[mt][0]);
            eacc[mt][1] = fmaf(tanhf_fast(c[mt][nt][2] + v0), w0, eacc[mt][1]);
            eacc[mt][1] = fmaf(tanhf_fast(c[mt][nt][3] + v1), w1, eacc[mt][1]);
        }
    }
    #pragma unroll
    for (int mt = 0; mt < 4; mt++) {
        #pragma unroll
        for (int h = 0; h < 2; h++) {
            eacc[mt][h] += __shfl_xor_sync(0xFFFFFFFFu, eacc[mt][h], 1);
            eacc[mt][h] += __shfl_xor_sync(0xFFFFFFFFu, eacc[mt][h], 2);
        }
    }
    float* e_sm = (float*)(smem + SM_E);
    if (qtid == 0) {
        #pragma unroll
        for (int mt = 0; mt < 4; mt++) {
            int rloc = wm * 64 + mt * 16 + qid;
            e_sm[wn * 128 + rloc]     = eacc[mt][0];
            e_sm[wn * 128 + rloc + 8] = eacc[mt][1];
        }
    }
    __syncthreads();
    {
        float e = e_sm[tid] + e_sm[128 + tid];
        g_e_part[(size_t)blockIdx.x * ROWS_TOTAL + row0 + tid] = e;
    }
}

// ---------------- kernel 3: softmax over S per batch ----------------
__global__ void softmax_kernel() {
    __shared__ float es[S_LEN];
    __shared__ float red[256];
    int b = blockIdx.x, tid = threadIdx.x;
    float lm = -1e30f;
    for (int i = tid; i < S_LEN; i += 256) {
        int row = b * S_LEN + i;
        float e = 0.f;
        #pragma unroll
        for (int p = 0; p < NPART; p++) e += g_e_part[(size_t)p * ROWS_TOTAL + row];
        es[i] = e;
        lm = fmaxf(lm, e);
    }
    red[tid] = lm; __syncthreads();
    for (int o = 128; o; o >>= 1) { if (tid < o) red[tid] = fmaxf(red[tid], red[tid + o]); __syncthreads(); }
    float mx = red[0]; __syncthreads();
    float ls = 0.f;
    for (int i = tid; i < S_LEN; i += 256) {
        float w = expf(es[i] - mx);
        es[i] = w; ls += w;
    }
    red[tid] = ls; __syncthreads();
    for (int o = 128; o; o >>= 1) { if (tid < o) red[tid] += red[tid + o]; __syncthreads(); }
    float inv = 1.f / red[0];
    for (int i = tid; i < S_LEN; i += 256) g_alpha[b * S_LEN + i] = es[i] * inv;
}

// ---------------- kernel 4: context partials (split-S x16, fp16 enc, uint4 loads) ----------------
__global__ void context_kernel() {
    __shared__ float al[128];
    int c = blockIdx.x, b = blockIdx.y, tid = threadIdx.x;   // 128 threads
    int s0 = c * (S_LEN / CTX_SPLIT);                         // 128 s per block
    al[tid] = g_alpha[b * S_LEN + s0 + tid];
    __syncthreads();
    float acc[8];
    #pragma unroll
    for (int q = 0; q < 8; q++) acc[q] = 0.f;
    const __half* base = g_enc_h + ((size_t)b * S_LEN + s0) * 1024 + tid * 8;
    #pragma unroll 4
    for (int s = 0; s < S_LEN / CTX_SPLIT; s++) {
        float a = al[s];
        uint4 pk = *(const uint4*)(base + (size_t)s * 1024);
        __half2 h0 = *(__half2*)&pk.x;
        __half2 h1 = *(__half2*)&pk.y;
        __half2 h2 = *(__half2*)&pk.z;
        __half2 h3 = *(__half2*)&pk.w;
        float2 f0 = __half22float2(h0);
        float2 f1 = __half22float2(h1);
        float2 f2 = __half22float2(h2);
        float2 f3 = __half22float2(h3);
        acc[0] = fmaf(a, f0.x, acc[0]); acc[1] = fmaf(a, f0.y, acc[1]);
        acc[2] = fmaf(a, f1.x, acc[2]); acc[3] = fmaf(a, f1.y, acc[3]);
        acc[4] = fmaf(a, f2.x, acc[4]); acc[5] = fmaf(a, f2.y, acc[5]);
        acc[6] = fmaf(a, f3.x, acc[6]); acc[7] = fmaf(a, f3.y, acc[7]);
    }
    float* dst = g_ctx_part + ((size_t)(c * 64 + b) * 1024) + tid * 8;
    *(float4*)dst       = make_float4(acc[0], acc[1], acc[2], acc[3]);
    *(float4*)(dst + 4) = make_float4(acc[4], acc[5], acc[6], acc[7]);
}

// ---------------- kernel 5: reduce partials -> out ----------------
__global__ void reduce_kernel(float* __restrict__ out) {
    int i = blockIdx.x * 256 + threadIdx.x;   // 65536
    float s = 0.f;
    #pragma unroll
    for (int c = 0; c < CTX_SPLIT; c++) s += g_ctx_part[(size_t)c * 65536 + i];
    out[i] = s;
}

// ---------------- launch ----------------
extern "C" void kernel_launch(void* const* d_in, const int* in_sizes, int n_in,
                              void* d_out, int out_size) {
    const float* hidden = (const float*)d_in[0];
    const float* enc    = (const float*)d_in[1];
    const float* W1     = (const float*)d_in[2];
    const float* b1     = (const float*)d_in[3];
    const float* W2     = (const float*)d_in[4];
    float* out = (float*)d_out;

    cudaFuncSetAttribute(gemm_tanh_kernel, cudaFuncAttributeMaxDynamicSharedMemorySize, SMEM_TOTAL);

    prep_kernel<<<PREP_BLOCKS, 256>>>(enc, W1, b1, hidden);
    gemm_tanh_kernel<<<dim3(NPART, ROWS_TOTAL / TILE_M), GEMM_THREADS, SMEM_TOTAL>>>(W2);
    softmax_kernel<<<64, 256>>>();
    context_kernel<<<dim3(CTX_SPLIT, 64), 128>>>();
    reduce_kernel<<<256, 256>>>(out);
}

// round 15
// speedup vs baseline: 1.0078x; 1.0078x over previous
#include <cuda_runtime.h>
#include <cuda.h>
#include <cuda_fp16.h>
#include <cstdint>

// ---------------- problem constants ----------------
#define B_BATCH 64
#define S_LEN   2048
#define D_DIM   1024
#define ROWS_TOTAL (B_BATCH * S_LEN)   // 131072

// ---------------- GEMM tiling ----------------
#define TILE_M 128
#define TILE_N 128
#define KC     64                      // k per stage (fp16 -> 128B rows)
#define KITERS (D_DIM / KC)            // 16
#define NPART  8                       // D_DIM / TILE_N
#define GEMM_THREADS 128               // 4 warps, 2m x 2n, warp tile 64x64
#define NSTAGES 3

#define A_STAGE_B (TILE_M * KC * 2)    // 16384 B
#define B_STAGE_B (TILE_N * KC * 2)    // 16384 B

#define SM_W2 0
#define SM_V  512
#define SM_E  1024                     // 256 floats
#define SM_A  2048
#define SM_B  (SM_A + NSTAGES * A_STAGE_B)        // 51200
#define SMEM_TOTAL (SM_B + NSTAGES * B_STAGE_B)   // 100352 B (2 CTAs/SM)

#define CTX_SPLIT 16                   // context split-S factor

// ---------------- scratch ----------------
__device__ __half g_enc_h[(size_t)ROWS_TOTAL * D_DIM];   // enc as fp16
__device__ __half g_w1e_h[D_DIM * D_DIM];                // W1e as fp16 (k-major)
__device__ float g_v[B_BATCH * D_DIM];                   // h@W1h^T + b1
__device__ float g_e_part[NPART * ROWS_TOTAL];           // per n-part partial e
__device__ float g_alpha[ROWS_TOTAL];
__device__ float g_ctx_part[CTX_SPLIT * B_BATCH * D_DIM];// split-S context partials

// ---------------- helpers ----------------
__device__ __forceinline__ uint32_t smem_u32(const void* p) {
    uint32_t a;
    asm("{ .reg .u64 t; cvta.to.shared.u64 t, %1; cvt.u32.u64 %0, t; }" : "=r"(a) : "l"(p));
    return a;
}
__device__ __forceinline__ void cp16(uint32_t smem_addr, const void* gptr) {
    asm volatile("cp.async.cg.shared.global [%0], [%1], 16;" :: "r"(smem_addr), "l"(gptr));
}
#define CP_COMMIT() asm volatile("cp.async.commit_group;" ::: "memory")
#define CP_WAIT(n)  asm volatile("cp.async.wait_group %0;" :: "n"(n) : "memory")

__device__ __forceinline__ void ldsm4(uint32_t* r, uint32_t addr) {
    asm volatile("ldmatrix.sync.aligned.m8n8.x4.shared.b16 {%0,%1,%2,%3}, [%4];"
        : "=r"(r[0]), "=r"(r[1]), "=r"(r[2]), "=r"(r[3]) : "r"(addr));
}
__device__ __forceinline__ void mma_f16(float* d, const uint32_t* a, uint32_t b0, uint32_t b1) {
    asm volatile(
        "mma.sync.aligned.m16n8k16.row.col.f32.f16.f16.f32 "
        "{%0,%1,%2,%3}, {%4,%5,%6,%7}, {%8,%9}, {%0,%1,%2,%3};"
        : "+f"(d[0]), "+f"(d[1]), "+f"(d[2]), "+f"(d[3])
        : "r"(a[0]), "r"(a[1]), "r"(a[2]), "r"(a[3]), "r"(b0), "r"(b1));
}
__device__ __forceinline__ float tanhf_fast(float x) {
    float t;
    asm("tanh.approx.f32 %0, %1;" : "=f"(t) : "f"(x));
    return t;
}

// ---------------- kernel 1: fused prep (v | pack W1e | conv enc) ----------------
#define PREP_BLOCKS (1024 + 512 + 65536)
__global__ void prep_kernel(const float* __restrict__ enc, const float* __restrict__ W1,
                            const float* __restrict__ b1, const float* __restrict__ hidden) {
    __shared__ float hs[1024];
    const int bid = blockIdx.x;
    const int tid = threadIdx.x;
    if (bid < 1024) {
        int b = bid & 63, yseg = bid >> 6;
        int w = tid >> 5, lane = tid & 31;
        for (int i = tid; i < 1024; i += 256) hs[i] = hidden[b * 1024 + i];
        __syncthreads();
        #pragma unroll
        for (int i = 0; i < 8; i++) {
            int d = yseg * 64 + w * 8 + i;
            const float* row = W1 + (size_t)d * 2048 + 1024;
            float acc = 0.f;
            for (int m = lane; m < 1024; m += 32) acc = fmaf(hs[m], row[m], acc);
            #pragma unroll
            for (int o = 16; o; o >>= 1) acc += __shfl_xor_sync(0xFFFFFFFFu, acc, o);
            if (lane == 0) g_v[b * 1024 + d] = acc + b1[d];
        }
    } else if (bid < 1536) {
        int t = (bid - 1024) * 256 + tid;
        size_t base = (size_t)t * 8;
        int d = (int)(base >> 10);
        int k = (int)(base & 1023);
        const float4* src = (const float4*)(W1 + (size_t)d * 2048 + k);
        float4 v0 = src[0], v1 = src[1];
        __half2 h[4];
        h[0] = __floats2half2_rn(v0.x, v0.y);
        h[1] = __floats2half2_rn(v0.z, v0.w);
        h[2] = __floats2half2_rn(v1.x, v1.y);
        h[3] = __floats2half2_rn(v1.z, v1.w);
        *(uint4*)(g_w1e_h + (size_t)d * 1024 + k) = *(uint4*)h;
    } else {
        size_t i = ((size_t)(bid - 1536) * 256 + tid) * 8;
        float4 v0 = *(const float4*)(enc + i);
        float4 v1 = *(const float4*)(enc + i + 4);
        __half2 h[4];
        h[0] = __floats2half2_rn(v0.x, v0.y);
        h[1] = __floats2half2_rn(v0.z, v0.w);
        h[2] = __floats2half2_rn(v1.x, v1.y);
        h[3] = __floats2half2_rn(v1.z, v1.w);
        *(uint4*)(g_enc_h + i) = *(uint4*)h;
    }
}

// ---------------- kernel 2: GEMM (mma.sync fp16) + tanh + W2-dot ----------------
// 128 threads, 4 warps: 2m x 2n; warp tile 64x64. 2 CTAs/SM.
// Round-13 structure (best measured): prefetch issued after ks0.
__global__ void __launch_bounds__(GEMM_THREADS, 2)
gemm_tanh_kernel(const float* __restrict__ W2) {
    extern __shared__ char smem[];
    const int tid = threadIdx.x;
    const int wid = tid >> 5;
    const int lane = tid & 31;
    const int wm = wid & 1;
    const int wn = wid >> 1;
    const int qid = lane >> 2;
    const int qtid = lane & 3;
    const int d0 = blockIdx.x * TILE_N;
    const int row0 = blockIdx.y * TILE_M;
    const int b = row0 / S_LEN;

    float* W2s = (float*)(smem + SM_W2);
    float* vs  = (float*)(smem + SM_V);
    W2s[tid] = W2[d0 + tid];
    vs[tid]  = g_v[b * 1024 + d0 + tid];

    const uint32_t sA = smem_u32(smem + SM_A);
    const uint32_t sB = smem_u32(smem + SM_B);

    auto load_stage = [&](int stg, int kc) {
        #pragma unroll
        for (int i = 0; i < 8; i++) {
            int j = tid + i * 128;
            int r = j >> 3, ck = j & 7;
            cp16(sA + stg * A_STAGE_B + (uint32_t)(r * 128 + ((ck ^ (r & 7)) << 4)),
                 g_enc_h + (size_t)(row0 + r) * 1024 + kc * KC + ck * 8);
        }
        #pragma unroll
        for (int i = 0; i < 8; i++) {
            int j = tid + i * 128;
            int n = j >> 3, ck = j & 7;
            cp16(sB + stg * B_STAGE_B + (uint32_t)(n * 128 + ((ck ^ (n & 7)) << 4)),
                 g_w1e_h + (size_t)(d0 + n) * 1024 + kc * KC + ck * 8);
        }
    };

    const int mlane = (lane & 7) | (lane & 8);
    const int cbitA = (lane >> 4) & 1;
    const int nlane = (lane & 7) | ((lane & 16) >> 1);
    const int cbitB = (lane >> 3) & 1;
    int rA0 = wm * 64 + mlane;
    int phA = rA0 & 7;
    int rB0 = wn * 64 + nlane;
    int phB = rB0 & 7;

    float c[4][8][4];
    #pragma unroll
    for (int mt = 0; mt < 4; mt++)
        #pragma unroll
        for (int nt = 0; nt < 8; nt++)
            #pragma unroll
            for (int q = 0; q < 4; q++) c[mt][nt][q] = 0.f;

    load_stage(0, 0); CP_COMMIT();
    load_stage(1, 1); CP_COMMIT();

    int cur = 0;
    for (int kc = 0; kc < KITERS; kc++) {
        CP_WAIT(1);
        __syncthreads();

        const uint32_t sAc = sA + cur * A_STAGE_B;
        const uint32_t sBc = sB + cur * B_STAGE_B;

        auto do_ks = [&](int ks) {
            uint32_t bb[8][2];
            #pragma unroll
            for (int ntp = 0; ntp < 4; ntp++) {
                uint32_t q[4];
                uint32_t addr = sBc + (uint32_t)((rB0 + ntp * 16) * 128)
                              + (uint32_t)((((2 * ks + cbitB) ^ phB)) << 4);
                ldsm4(q, addr);
                bb[ntp * 2][0] = q[0]; bb[ntp * 2][1] = q[1];
                bb[ntp * 2 + 1][0] = q[2]; bb[ntp * 2 + 1][1] = q[3];
            }
            uint32_t a[4][4];
            ldsm4(a[0], sAc + (uint32_t)(rA0 * 128) + (uint32_t)((((2 * ks + cbitA) ^ phA)) << 4));
            #pragma unroll
            for (int mt = 0; mt < 4; mt++) {
                if (mt + 1 < 4)
                    ldsm4(a[mt + 1], sAc + (uint32_t)((rA0 + (mt + 1) * 16) * 128)
                                   + (uint32_t)((((2 * ks + cbitA) ^ phA)) << 4));
                #pragma unroll
                for (int nt = 0; nt < 8; nt++)
                    mma_f16(c[mt][nt], a[mt], bb[nt][0], bb[nt][1]);
            }
        };

        do_ks(0);                                   // fragments of the new stage first

        if (kc + 2 < KITERS) {                      // then issue prefetch stores
            int nxt = cur + 2; if (nxt >= NSTAGES) nxt -= NSTAGES;
            load_stage(nxt, kc + 2);
        }
        CP_COMMIT();

        do_ks(1);
        do_ks(2);
        do_ks(3);

        cur++; if (cur >= NSTAGES) cur -= NSTAGES;
    }

    // ---------------- fused epilogue ----------------
    float eacc[4][2];
    #pragma unroll
    for (int mt = 0; mt < 4; mt++) { eacc[mt][0] = 0.f; eacc[mt][1] = 0.f; }
    #pragma unroll
    for (int mt = 0; mt < 4; mt++) {
        #pragma unroll
        for (int nt = 0; nt < 8; nt++) {
            int n0 = wn * 64 + nt * 8 + 2 * qtid;
            int n1 = n0 + 1;
            float w0 = W2s[n0], w1 = W2s[n1];
            float v0 = vs[n0],  v1 = vs[n1];
            eacc[mt][0] = fmaf(tanhf_fast(c[mt][nt][0] + v0), w0, eacc[mt][0]);
            eacc[mt][0] = fmaf(tanhf_fast(c[mt][nt][1] + v1), w1, eacc[mt][0]);
            eacc[mt][1] = fmaf(tanhf_fast(c[mt][nt][2] + v0), w0, eacc[mt][1]);
            eacc[mt][1] = fmaf(tanhf_fast(c[mt][nt][3] + v1), w1, eacc[mt][1]);
        }
    }
    #pragma unroll
    for (int mt = 0; mt < 4; mt++) {
        #pragma unroll
        for (int h = 0; h < 2; h++) {
            eacc[mt][h] += __shfl_xor_sync(0xFFFFFFFFu, eacc[mt][h], 1);
            eacc[mt][h] += __shfl_xor_sync(0xFFFFFFFFu, eacc[mt][h], 2);
        }
    }
    float* e_sm = (float*)(smem + SM_E);
    if (qtid == 0) {
        #pragma unroll
        for (int mt = 0; mt < 4; mt++) {
            int rloc = wm * 64 + mt * 16 + qid;
            e_sm[wn * 128 + rloc]     = eacc[mt][0];
            e_sm[wn * 128 + rloc + 8] = eacc[mt][1];
        }
    }
    __syncthreads();
    {
        float e = e_sm[tid] + e_sm[128 + tid];
        g_e_part[(size_t)blockIdx.x * ROWS_TOTAL + row0 + tid] = e;
    }
}

// ---------------- kernel 3: softmax over S per batch (float4 e_part reads) ----------------
__global__ void softmax_kernel() {
    __shared__ float es[S_LEN];
    __shared__ float red[256];
    int b = blockIdx.x, tid = threadIdx.x;
    float lm = -1e30f;
    // 2048 e-values per batch = 512 float4; 256 threads x 2 iterations
    for (int i4 = tid; i4 < S_LEN / 4; i4 += 256) {
        int row4 = b * S_LEN / 4 + i4;
        float4 e = make_float4(0.f, 0.f, 0.f, 0.f);
        #pragma unroll
        for (int p = 0; p < NPART; p++) {
            float4 t = *((const float4*)g_e_part + (size_t)p * (ROWS_TOTAL / 4) + row4);
            e.x += t.x; e.y += t.y; e.z += t.z; e.w += t.w;
        }
        *((float4*)es + i4) = e;
        lm = fmaxf(lm, fmaxf(fmaxf(e.x, e.y), fmaxf(e.z, e.w)));
    }
    red[tid] = lm; __syncthreads();
    for (int o = 128; o; o >>= 1) { if (tid < o) red[tid] = fmaxf(red[tid], red[tid + o]); __syncthreads(); }
    float mx = red[0]; __syncthreads();
    float ls = 0.f;
    for (int i = tid; i < S_LEN; i += 256) {
        float w = expf(es[i] - mx);
        es[i] = w; ls += w;
    }
    red[tid] = ls; __syncthreads();
    for (int o = 128; o; o >>= 1) { if (tid < o) red[tid] += red[tid + o]; __syncthreads(); }
    float inv = 1.f / red[0];
    for (int i = tid; i < S_LEN; i += 256) g_alpha[b * S_LEN + i] = es[i] * inv;
}

// ---------------- kernel 4: context partials (split-S x16, fp16 enc, uint4 loads) ----------------
__global__ void context_kernel() {
    __shared__ float al[128];
    int c = blockIdx.x, b = blockIdx.y, tid = threadIdx.x;   // 128 threads
    int s0 = c * (S_LEN / CTX_SPLIT);                         // 128 s per block
    al[tid] = g_alpha[b * S_LEN + s0 + tid];
    __syncthreads();
    float acc[8];
    #pragma unroll
    for (int q = 0; q < 8; q++) acc[q] = 0.f;
    const __half* base = g_enc_h + ((size_t)b * S_LEN + s0) * 1024 + tid * 8;
    #pragma unroll 4
    for (int s = 0; s < S_LEN / CTX_SPLIT; s++) {
        float a = al[s];
        uint4 pk = *(const uint4*)(base + (size_t)s * 1024);
        __half2 h0 = *(__half2*)&pk.x;
        __half2 h1 = *(__half2*)&pk.y;
        __half2 h2 = *(__half2*)&pk.z;
        __half2 h3 = *(__half2*)&pk.w;
        float2 f0 = __half22float2(h0);
        float2 f1 = __half22float2(h1);
        float2 f2 = __half22float2(h2);
        float2 f3 = __half22float2(h3);
        acc[0] = fmaf(a, f0.x, acc[0]); acc[1] = fmaf(a, f0.y, acc[1]);
        acc[2] = fmaf(a, f1.x, acc[2]); acc[3] = fmaf(a, f1.y, acc[3]);
        acc[4] = fmaf(a, f2.x, acc[4]); acc[5] = fmaf(a, f2.y, acc[5]);
        acc[6] = fmaf(a, f3.x, acc[6]); acc[7] = fmaf(a, f3.y, acc[7]);
    }
    float* dst = g_ctx_part + ((size_t)(c * 64 + b) * 1024) + tid * 8;
    *(float4*)dst       = make_float4(acc[0], acc[1], acc[2], acc[3]);
    *(float4*)(dst + 4) = make_float4(acc[4], acc[5], acc[6], acc[7]);
}

// ---------------- kernel 5: reduce partials -> out ----------------
__global__ void reduce_kernel(float* __restrict__ out) {
    int i = blockIdx.x * 256 + threadIdx.x;   // 65536
    float s = 0.f;
    #pragma unroll
    for (int c = 0; c < CTX_SPLIT; c++) s += g_ctx_part[(size_t)c * 65536 + i];
    out[i] = s;
}

// ---------------- launch ----------------
extern "C" void kernel_launch(void* const* d_in, const int* in_sizes, int n_in,
                              void* d_out, int out_size) {
    const float* hidden = (const float*)d_in[0];
    const float* enc    = (const float*)d_in[1];
    const float* W1     = (const float*)d_in[2];
    const float* b1     = (const float*)d_in[3];
    const float* W2     = (const float*)d_in[4];
    float* out = (float*)d_out;

    cudaFuncSetAttribute(gemm_tanh_kernel, cudaFuncAttributeMaxDynamicSharedMemorySize, SMEM_TOTAL);

    prep_kernel<<<PREP_BLOCKS, 256>>>(enc, W1, b1, hidden);
    gemm_tanh_kernel<<<dim3(NPART, ROWS_TOTAL / TILE_M), GEMM_THREADS, SMEM_TOTAL>>>(W2);
    softmax_kernel<<<64, 256>>>();
    context_kernel<<<dim3(CTX_SPLIT, 64), 128>>>();
    reduce_kernel<<<256, 256>>>(out);
}